// round 1
// baseline (speedup 1.0000x reference)
#include <cuda_runtime.h>
#include <math.h>

#define C_DIM 256
#define N_DIM 4096
#define B_DIM 2
#define HEADS 8
#define HD 32
#define BCN (B_DIM * C_DIM * N_DIM)   // 2097152

// ---------------- scratch (no allocations allowed) ----------------
__device__ float g_scale[B_DIM * C_DIM];
__device__ float g_shift[B_DIM * C_DIM];
__device__ float g_qkv[3 * BCN];       // Q,K,V each [B][C][N]
__device__ float g_attnout[BCN];       // attention output [B][C][N]

// ---------------- GroupNorm stats -> per-channel scale/shift ----------------
// grid: 16 blocks (b*8+g), 256 threads. Group data is contiguous: 32ch*4096 = 131072 floats.
__global__ __launch_bounds__(256) void gn_stats_kernel(
    const float* __restrict__ x, const float* __restrict__ gw,
    const float* __restrict__ gb, float* __restrict__ scl, float* __restrict__ shf)
{
    int bg = blockIdx.x;
    int b = bg >> 3, g = bg & 7;
    const float* p = x + (size_t)(b * C_DIM + g * 32) * N_DIM;
    float s = 0.f, s2 = 0.f;
    for (int i = threadIdx.x; i < 131072 / 4; i += 256) {
        float4 v = reinterpret_cast<const float4*>(p)[i];
        s  += v.x + v.y + v.z + v.w;
        s2 += v.x * v.x + v.y * v.y + v.z * v.z + v.w * v.w;
    }
    __shared__ float rs[256], rs2[256];
    rs[threadIdx.x] = s; rs2[threadIdx.x] = s2;
    __syncthreads();
    for (int st = 128; st; st >>= 1) {
        if (threadIdx.x < st) {
            rs[threadIdx.x]  += rs[threadIdx.x + st];
            rs2[threadIdx.x] += rs2[threadIdx.x + st];
        }
        __syncthreads();
    }
    __shared__ float mu_s, rstd_s;
    if (threadIdx.x == 0) {
        float m = rs[0] * (1.f / 131072.f);
        float var = rs2[0] * (1.f / 131072.f) - m * m;
        mu_s = m;
        rstd_s = rsqrtf(var + 1e-5f);
    }
    __syncthreads();
    if (threadIdx.x < 32) {
        int c = g * 32 + threadIdx.x;
        float sc = gw[c] * rstd_s;
        scl[b * C_DIM + c] = sc;
        shf[b * C_DIM + c] = gb[c] - mu_s * sc;
    }
}

// ---------------- generic 256-K GEMM: Y[b,o,n] = sum_c W[o,c]*(X[b,c,n]*s+t) + bias (+resid) ----
// grid: (64 n-tiles, 4 o-tiles, 2 batches); block 256; tile 64o x 64n, BK=32; 4x4 micro-tile.
__global__ __launch_bounds__(256) void gemm256_kernel(
    const float* __restrict__ W, const float* __restrict__ bias,
    const float* __restrict__ X, const float* __restrict__ scale,
    const float* __restrict__ shift, const float* __restrict__ resid,
    float* __restrict__ Y)
{
    const int n0 = blockIdx.x * 64;
    const int o0 = blockIdx.y * 64;
    const int b  = blockIdx.z;
    const int tid = threadIdx.x;
    const int nt = tid & 15, ot = tid >> 4;

    __shared__ float As[32][65];                      // [k][o], transposed store (conflict-free)
    __shared__ __align__(16) float Bs[32][68];        // [k][n], float4-aligned rows

    const size_t xbase = (size_t)b * C_DIM * N_DIM;
    float acc[4][4] = {};

    for (int k0 = 0; k0 < C_DIM; k0 += 32) {
        // A tile: W[o0+o][k0+c], 64x32, transposed into As[c][o]
        #pragma unroll
        for (int r = 0; r < 2; r++) {
            int idx = tid + r * 256;
            int o = idx >> 3, c4 = (idx & 7) << 2;
            float4 w4 = *reinterpret_cast<const float4*>(W + (size_t)(o0 + o) * C_DIM + k0 + c4);
            As[c4 + 0][o] = w4.x; As[c4 + 1][o] = w4.y;
            As[c4 + 2][o] = w4.z; As[c4 + 3][o] = w4.w;
        }
        // B tile: X[b][k0+c][n0+n], 32x64, apply groupnorm scale/shift on the fly
        #pragma unroll
        for (int r = 0; r < 2; r++) {
            int idx = tid + r * 256;
            int c = idx >> 4, n4 = (idx & 15) << 2;
            float4 v = *reinterpret_cast<const float4*>(X + xbase + (size_t)(k0 + c) * N_DIM + n0 + n4);
            if (scale != nullptr) {
                float s = scale[b * C_DIM + k0 + c];
                float t = shift[b * C_DIM + k0 + c];
                v.x = fmaf(v.x, s, t); v.y = fmaf(v.y, s, t);
                v.z = fmaf(v.z, s, t); v.w = fmaf(v.w, s, t);
            }
            *reinterpret_cast<float4*>(&Bs[c][n4]) = v;
        }
        __syncthreads();
        #pragma unroll
        for (int k = 0; k < 32; k++) {
            float a0 = As[k][(ot << 2) + 0];
            float a1 = As[k][(ot << 2) + 1];
            float a2 = As[k][(ot << 2) + 2];
            float a3 = As[k][(ot << 2) + 3];
            float4 bv = *reinterpret_cast<const float4*>(&Bs[k][nt << 2]);
            acc[0][0] += a0 * bv.x; acc[0][1] += a0 * bv.y; acc[0][2] += a0 * bv.z; acc[0][3] += a0 * bv.w;
            acc[1][0] += a1 * bv.x; acc[1][1] += a1 * bv.y; acc[1][2] += a1 * bv.z; acc[1][3] += a1 * bv.w;
            acc[2][0] += a2 * bv.x; acc[2][1] += a2 * bv.y; acc[2][2] += a2 * bv.z; acc[2][3] += a2 * bv.w;
            acc[3][0] += a3 * bv.x; acc[3][1] += a3 * bv.y; acc[3][2] += a3 * bv.z; acc[3][3] += a3 * bv.w;
        }
        __syncthreads();
    }
    #pragma unroll
    for (int i = 0; i < 4; i++) {
        int o = o0 + (ot << 2) + i;
        float bo = bias[o];
        size_t off = xbase + (size_t)o * N_DIM + n0 + (nt << 2);
        float4 v;
        v.x = acc[i][0] + bo; v.y = acc[i][1] + bo;
        v.z = acc[i][2] + bo; v.w = acc[i][3] + bo;
        if (resid != nullptr) {
            float4 rr = *reinterpret_cast<const float4*>(resid + off);
            v.x += rr.x; v.y += rr.y; v.z += rr.z; v.w += rr.w;
        }
        *reinterpret_cast<float4*>(Y + off) = v;
    }
}

// ---------------- Flash attention: 64q x 64m tiles, D=32 ----------------
// grid: (64 q-blocks, 8 heads, 2 batches); 256 threads.
__global__ __launch_bounds__(256) void flash_kernel(
    const float* __restrict__ qkv, float* __restrict__ aout)
{
    const int q0 = blockIdx.x * 64;
    const int h  = blockIdx.y;
    const int b  = blockIdx.z;
    const int tid = threadIdx.x;

    __shared__ __align__(16) float Qs[32][68];
    __shared__ __align__(16) float Ks[32][68];
    __shared__ float Vt[64][33];                 // transposed V: [m][d], conflict-free scalar reads
    __shared__ __align__(16) float Ps[64][68];   // P tile; reused as O-transpose buffer at end
    __shared__ float Ms[64], Ls[64], Corr[64], Nm[64];

    const size_t headoff = (size_t)(b * C_DIM + h * HD) * N_DIM;
    const float* Qg = qkv + headoff;
    const float* Kg = qkv + (size_t)BCN + headoff;
    const float* Vg = qkv + 2ull * BCN + headoff;

    // load Q tile, pre-scaled by 1/sqrt(32)
    const float qsc = 0.17677669529663687f;
    #pragma unroll
    for (int r = 0; r < 2; r++) {
        int idx = tid + r * 256;
        int d = idx >> 4, c4 = (idx & 15) << 2;
        float4 v = *reinterpret_cast<const float4*>(Qg + (size_t)d * N_DIM + q0 + c4);
        v.x *= qsc; v.y *= qsc; v.z *= qsc; v.w *= qsc;
        *reinterpret_cast<float4*>(&Qs[d][c4]) = v;
    }
    if (tid < 64) { Ms[tid] = -1e30f; Ls[tid] = 0.f; }

    const int mt = tid & 15, qt = tid >> 4;      // layout A: S[qt*4+i][mt*4+j]
    const int dt = tid & 7,  qt2 = tid >> 3;     // layout B: O[qt2*2+r][dt*4+k]
    const int d0 = dt << 2;
    float acc[2][4] = {};

    for (int m0 = 0; m0 < N_DIM; m0 += 64) {
        __syncthreads();
        // K tile [d][m]
        #pragma unroll
        for (int r = 0; r < 2; r++) {
            int idx = tid + r * 256;
            int d = idx >> 4, m4 = (idx & 15) << 2;
            float4 v = *reinterpret_cast<const float4*>(Kg + (size_t)d * N_DIM + m0 + m4);
            *reinterpret_cast<float4*>(&Ks[d][m4]) = v;
        }
        // V tile transposed -> Vt[m][d]
        #pragma unroll
        for (int r = 0; r < 2; r++) {
            int idx = tid + r * 256;
            int d = idx >> 4, m4 = (idx & 15) << 2;
            float4 v = *reinterpret_cast<const float4*>(Vg + (size_t)d * N_DIM + m0 + m4);
            Vt[m4 + 0][d] = v.x; Vt[m4 + 1][d] = v.y;
            Vt[m4 + 2][d] = v.z; Vt[m4 + 3][d] = v.w;
        }
        __syncthreads();

        // S = Q^T K (already scaled)
        float s[4][4] = {};
        #pragma unroll
        for (int d = 0; d < 32; d++) {
            float4 qv = *reinterpret_cast<const float4*>(&Qs[d][qt << 2]);
            float4 kv = *reinterpret_cast<const float4*>(&Ks[d][mt << 2]);
            s[0][0] += qv.x * kv.x; s[0][1] += qv.x * kv.y; s[0][2] += qv.x * kv.z; s[0][3] += qv.x * kv.w;
            s[1][0] += qv.y * kv.x; s[1][1] += qv.y * kv.y; s[1][2] += qv.y * kv.z; s[1][3] += qv.y * kv.w;
            s[2][0] += qv.z * kv.x; s[2][1] += qv.z * kv.y; s[2][2] += qv.z * kv.z; s[2][3] += qv.z * kv.w;
            s[3][0] += qv.w * kv.x; s[3][1] += qv.w * kv.y; s[3][2] += qv.w * kv.z; s[3][3] += qv.w * kv.w;
        }
        // online softmax: row max across 16 mt lanes
        #pragma unroll
        for (int i = 0; i < 4; i++) {
            float r = fmaxf(fmaxf(s[i][0], s[i][1]), fmaxf(s[i][2], s[i][3]));
            #pragma unroll
            for (int off = 8; off; off >>= 1)
                r = fmaxf(r, __shfl_xor_sync(0xffffffffu, r, off));
            if (mt == 0) {
                int q = (qt << 2) + i;
                float nm = fmaxf(Ms[q], r);
                Corr[q] = __expf(Ms[q] - nm);
                Ms[q] = nm;
                Nm[q] = nm;
            }
        }
        __syncthreads();
        // P = exp(S - nm); row sums; write P tile
        #pragma unroll
        for (int i = 0; i < 4; i++) {
            int q = (qt << 2) + i;
            float nm = Nm[q];
            float p0 = __expf(s[i][0] - nm);
            float p1 = __expf(s[i][1] - nm);
            float p2 = __expf(s[i][2] - nm);
            float p3 = __expf(s[i][3] - nm);
            float4 pv = {p0, p1, p2, p3};
            *reinterpret_cast<float4*>(&Ps[q][mt << 2]) = pv;
            float rs = (p0 + p1) + (p2 + p3);
            #pragma unroll
            for (int off = 8; off; off >>= 1)
                rs += __shfl_xor_sync(0xffffffffu, rs, off);
            if (mt == 0) Ls[q] = Ls[q] * Corr[q] + rs;
        }
        __syncthreads();
        // O = O*corr + P @ V^T
        {
            float c0 = Corr[qt2 * 2], c1 = Corr[qt2 * 2 + 1];
            #pragma unroll
            for (int k = 0; k < 4; k++) { acc[0][k] *= c0; acc[1][k] *= c1; }
            #pragma unroll 4
            for (int m = 0; m < 64; m++) {
                float p0 = Ps[qt2 * 2][m];
                float p1 = Ps[qt2 * 2 + 1][m];
                float v0 = Vt[m][d0], v1 = Vt[m][d0 + 1], v2 = Vt[m][d0 + 2], v3 = Vt[m][d0 + 3];
                acc[0][0] += p0 * v0; acc[0][1] += p0 * v1; acc[0][2] += p0 * v2; acc[0][3] += p0 * v3;
                acc[1][0] += p1 * v0; acc[1][1] += p1 * v1; acc[1][2] += p1 * v2; acc[1][3] += p1 * v3;
            }
        }
    }
    __syncthreads();
    // normalize and transpose via smem (reuse Ps as [q][d] stride 33)
    {
        float inv0 = 1.f / Ls[qt2 * 2];
        float inv1 = 1.f / Ls[qt2 * 2 + 1];
        float* Os = &Ps[0][0];
        #pragma unroll
        for (int k = 0; k < 4; k++) {
            Os[(qt2 * 2) * 33 + d0 + k]     = acc[0][k] * inv0;
            Os[(qt2 * 2 + 1) * 33 + d0 + k] = acc[1][k] * inv1;
        }
    }
    __syncthreads();
    {
        float* Os = &Ps[0][0];
        float* outp = aout + headoff;
        #pragma unroll
        for (int r = 0; r < 8; r++) {
            int idx = tid + r * 256;
            int d = idx >> 6, q = idx & 63;
            outp[(size_t)d * N_DIM + q0 + q] = Os[q * 33 + d];
        }
    }
}

// ---------------- launch ----------------
extern "C" void kernel_launch(void* const* d_in, const int* in_sizes, int n_in,
                              void* d_out, int out_size)
{
    const float* x    = (const float*)d_in[0];
    const float* gn_w = (const float*)d_in[1];
    const float* gn_b = (const float*)d_in[2];
    const float* wq   = (const float*)d_in[3];
    const float* bq   = (const float*)d_in[4];
    const float* wk   = (const float*)d_in[5];
    const float* bk   = (const float*)d_in[6];
    const float* wv   = (const float*)d_in[7];
    const float* bv   = (const float*)d_in[8];
    const float* wo   = (const float*)d_in[9];
    const float* bo   = (const float*)d_in[10];
    float* out = (float*)d_out;

    float *scl, *shf, *qkv, *attn;
    cudaGetSymbolAddress((void**)&scl,  g_scale);
    cudaGetSymbolAddress((void**)&shf,  g_shift);
    cudaGetSymbolAddress((void**)&qkv,  g_qkv);
    cudaGetSymbolAddress((void**)&attn, g_attnout);

    gn_stats_kernel<<<16, 256>>>(x, gn_w, gn_b, scl, shf);

    dim3 ggrid(64, 4, 2);
    gemm256_kernel<<<ggrid, 256>>>(wq, bq, x, scl, shf, nullptr, qkv);
    gemm256_kernel<<<ggrid, 256>>>(wk, bk, x, scl, shf, nullptr, qkv + BCN);
    gemm256_kernel<<<ggrid, 256>>>(wv, bv, x, scl, shf, nullptr, qkv + 2 * (size_t)BCN);

    dim3 fgrid(64, HEADS, B_DIM);
    flash_kernel<<<fgrid, 256>>>(qkv, attn);

    gemm256_kernel<<<ggrid, 256>>>(wo, bo, attn, nullptr, nullptr, x, out);
}